// round 6
// baseline (speedup 1.0000x reference)
#include <cuda_runtime.h>
#include <cstdint>
#include <cstddef>

#define Bsz   16384
#define DIN   768
#define Hdim  1024
#define Ldim  128
#define Kcb   8192
#define Edim  128
#define NLq   3

// ---------------------------------------------------------------------------
// Scratch (device globals; no allocation allowed)
// ---------------------------------------------------------------------------
__device__ float g_h1[Bsz * Hdim];
__device__ float g_h2[Bsz * Hdim];
__device__ float g_z[Bsz * Ldim];       // doubles as "cur"
__device__ float g_nr[Bsz * Ldim];
__device__ float g_f[Bsz * Ldim];
__device__ float g_quant[Bsz * Ldim];
__device__ float g_rowloss[Bsz];
__device__ int   g_idx[Bsz];
__device__ float g_cbnorm[NLq * Kcb];

// ---------------------------------------------------------------------------
// Generic tiled SGEMM: C[M,N] = act(A[M,K] @ W[K,N] + bias[N]) in fp32.
// BM=BN=64, BK=16, 256 threads, 4x4 register tile.
// ---------------------------------------------------------------------------
template <bool RELU>
__global__ __launch_bounds__(256) void gemm_kernel(
    const float* __restrict__ A, const float* __restrict__ W,
    const float* __restrict__ bias, float* __restrict__ C,
    int M, int N, int K)
{
    __shared__ float As[16 * 65];   // [k][m], padded
    __shared__ float Ws[16 * 64];   // [k][n]

    const int tid = threadIdx.x;
    const int tx = tid & 15;        // col group
    const int ty = tid >> 4;        // row group
    const int row0 = blockIdx.y * 64;
    const int col0 = blockIdx.x * 64;

    float acc[4][4] = {};

    for (int k0 = 0; k0 < K; k0 += 16) {
        #pragma unroll
        for (int i = tid; i < 64 * 16; i += 256) {
            int m = i >> 4, k = i & 15;
            As[k * 65 + m] = A[(size_t)(row0 + m) * K + k0 + k];
        }
        #pragma unroll
        for (int i = tid; i < 16 * 64; i += 256) {
            int k = i >> 6, n = i & 63;
            Ws[k * 64 + n] = W[(size_t)(k0 + k) * N + col0 + n];
        }
        __syncthreads();
        #pragma unroll
        for (int k = 0; k < 16; k++) {
            float a[4], w[4];
            #pragma unroll
            for (int i = 0; i < 4; i++) a[i] = As[k * 65 + ty * 4 + i];
            #pragma unroll
            for (int j = 0; j < 4; j++) w[j] = Ws[k * 64 + tx * 4 + j];
            #pragma unroll
            for (int i = 0; i < 4; i++)
                #pragma unroll
                for (int j = 0; j < 4; j++)
                    acc[i][j] = fmaf(a[i], w[j], acc[i][j]);
        }
        __syncthreads();
    }

    #pragma unroll
    for (int i = 0; i < 4; i++) {
        int m = row0 + ty * 4 + i;
        #pragma unroll
        for (int j = 0; j < 4; j++) {
            int n = col0 + tx * 4 + j;
            float v = __fadd_rn(acc[i][j], bias[n]);
            if (RELU) v = fmaxf(v, 0.0f);
            C[(size_t)m * N + n] = v;
        }
    }
}

// ---------------------------------------------------------------------------
// LayerNorm over rows of 128 (eps=1e-5, biased variance). IEEE sqrt + div.
// Explicit mul/add (no fma contraction) to mirror elementwise XLA ops.
// ---------------------------------------------------------------------------
__global__ __launch_bounds__(128) void ln_kernel(
    const float* __restrict__ x, const float* __restrict__ g,
    const float* __restrict__ b, float* __restrict__ out)
{
    const int row = blockIdx.x;
    const int j = threadIdx.x;
    __shared__ float sm[4];

    float v = x[(size_t)row * Ldim + j];

    float s = v;
    #pragma unroll
    for (int o = 16; o; o >>= 1) s += __shfl_down_sync(0xffffffffu, s, o);
    if ((j & 31) == 0) sm[j >> 5] = s;
    __syncthreads();
    float mean = (sm[0] + sm[1] + sm[2] + sm[3]) * (1.0f / 128.0f);
    __syncthreads();

    float t = __fsub_rn(v, mean);
    s = __fmul_rn(t, t);
    #pragma unroll
    for (int o = 16; o; o >>= 1) s += __shfl_down_sync(0xffffffffu, s, o);
    if ((j & 31) == 0) sm[j >> 5] = s;
    __syncthreads();
    float var = (sm[0] + sm[1] + sm[2] + sm[3]) * (1.0f / 128.0f);

    float denom = sqrtf(__fadd_rn(var, 1e-5f));   // IEEE sqrt
    float r = __fdiv_rn(t, denom);                 // IEEE div
    out[(size_t)row * Ldim + j] = __fadd_rn(__fmul_rn(r, g[j]), b[j]);
}

// ---------------------------------------------------------------------------
// Codebook row squared norms (round each square, then add)
// ---------------------------------------------------------------------------
__global__ __launch_bounds__(128) void cbnorm_kernel(
    const float* __restrict__ cb, float* __restrict__ out)
{
    const int r = blockIdx.x;
    const int j = threadIdx.x;
    __shared__ float sm[4];
    float v = cb[(size_t)r * Edim + j];
    float s = __fmul_rn(v, v);
    #pragma unroll
    for (int o = 16; o; o >>= 1) s += __shfl_down_sync(0xffffffffu, s, o);
    if ((j & 31) == 0) sm[j >> 5] = s;
    __syncthreads();
    if (j == 0) out[r] = sm[0] + sm[1] + sm[2] + sm[3];
}

// ---------------------------------------------------------------------------
// Reparameterize + init: z = mu + eps*exp(0.5*lv); quant = 0; rowloss = 0
// ---------------------------------------------------------------------------
__global__ __launch_bounds__(256) void init_kernel(
    const float* __restrict__ mu, const float* __restrict__ lv,
    const float* __restrict__ eps, float* __restrict__ z,
    float* __restrict__ quant, float* __restrict__ rowloss)
{
    int i = blockIdx.x * blockDim.x + threadIdx.x;
    if (i < Bsz * Ldim) {
        float e = expf(__fmul_rn(0.5f, lv[i]));
        float zz = __fadd_rn(mu[i], __fmul_rn(eps[i], e));
        z[i] = zz;
        quant[i] = 0.0f;
    }
    if (i < Bsz) rowloss[i] = 0.0f;
}

// ---------------------------------------------------------------------------
// Nearest-code search for 64 rows of f over K=8192 codes (pure fp32).
// fn = sum of fl(f*f) sequential; dot = sequential fmaf over e (SGEMM-like);
// d = fl(fl(fn + cbn) - 2*dot). First-min tie-break (jnp.argmin).
// ---------------------------------------------------------------------------
__global__ __launch_bounds__(256) void argmin_kernel(
    const float* __restrict__ f, const float* __restrict__ cb,
    const float* __restrict__ cbn, int* __restrict__ idxout)
{
    extern __shared__ float sm[];
    float* fsT  = sm;                    // [128][65]  (e-major, padded)
    float* cbsT = sm + 128 * 65;         // [128][65]
    float* fn   = sm + 2 * 128 * 65;     // [64]

    const int tid = threadIdx.x;
    const int tx = tid & 15;
    const int ty = tid >> 4;
    const int row0 = blockIdx.x * 64;

    for (int i = tid; i < 64 * 128; i += 256) {
        int r = i >> 7, e = i & 127;
        fsT[e * 65 + r] = f[(size_t)(row0 + r) * Edim + e];
    }
    __syncthreads();
    if (tid < 64) {
        float s = 0.0f;
        #pragma unroll 8
        for (int e = 0; e < 128; e++) {
            float v = fsT[e * 65 + tid];
            s = __fadd_rn(s, __fmul_rn(v, v));
        }
        fn[tid] = s;
    }

    float bestv[4];
    int   besti[4];
    #pragma unroll
    for (int i = 0; i < 4; i++) { bestv[i] = 3.4e38f; besti[i] = 0; }

    for (int kc = 0; kc < Kcb; kc += 64) {
        __syncthreads();   // protect cbsT (and fn on first iter)
        for (int i = tid; i < 64 * 128; i += 256) {
            int r = i >> 7, e = i & 127;
            cbsT[e * 65 + r] = cb[(size_t)(kc + r) * Edim + e];
        }
        __syncthreads();

        float acc[4][4] = {};
        #pragma unroll 8
        for (int e = 0; e < 128; e++) {
            float a[4], bb[4];
            #pragma unroll
            for (int i = 0; i < 4; i++) a[i] = fsT[e * 65 + ty * 4 + i];
            #pragma unroll
            for (int j = 0; j < 4; j++) bb[j] = cbsT[e * 65 + tx * 4 + j];
            #pragma unroll
            for (int i = 0; i < 4; i++)
                #pragma unroll
                for (int j = 0; j < 4; j++)
                    acc[i][j] = fmaf(a[i], bb[j], acc[i][j]);
        }

        #pragma unroll
        for (int j = 0; j < 4; j++) {
            int k = kc + tx * 4 + j;
            float c = cbn[k];
            #pragma unroll
            for (int i = 0; i < 4; i++) {
                float t1 = __fadd_rn(fn[ty * 4 + i], c);
                float d  = __fsub_rn(t1, __fmul_rn(2.0f, acc[i][j]));
                if (d < bestv[i]) { bestv[i] = d; besti[i] = k; }
            }
        }
    }

    __syncthreads();
    float* rv = fsT;                    // reuse
    int*   ri = (int*)(fsT + 64 * 16);
    #pragma unroll
    for (int i = 0; i < 4; i++) {
        rv[(ty * 4 + i) * 16 + tx] = bestv[i];
        ri[(ty * 4 + i) * 16 + tx] = besti[i];
    }
    __syncthreads();
    if (tid < 64) {
        float bv = rv[tid * 16];
        int   bi = ri[tid * 16];
        #pragma unroll
        for (int t = 1; t < 16; t++) {
            float v = rv[tid * 16 + t];
            int   ii = ri[tid * 16 + t];
            if (v < bv || (v == bv && ii < bi)) { bv = v; bi = ii; }
        }
        idxout[row0 + tid] = bi;
    }
}

// ---------------------------------------------------------------------------
// Gather code row, project through q_out, then apply straight-through with
// the reference's EXACT rounding:  q_st = fl( nr + fl(q - nr) ).
// quant += q_st ; cur -= q_st ; rowloss += sum((q - nr)^2).
// One block of 128 threads per batch row.
// ---------------------------------------------------------------------------
__global__ __launch_bounds__(128) void gather_update_kernel(
    const int* __restrict__ idx, const float* __restrict__ cb,
    const float* __restrict__ w, const float* __restrict__ bias,
    const float* __restrict__ nr, float* __restrict__ quant,
    float* __restrict__ cur, float* __restrict__ rowloss)
{
    const int b = blockIdx.x;
    const int j = threadIdx.x;
    __shared__ float crow[128];
    __shared__ float red[4];

    const int k = idx[b];
    crow[j] = cb[(size_t)k * Edim + j];
    __syncthreads();

    float acc = 0.0f;
    #pragma unroll 8
    for (int e = 0; e < 128; e++)
        acc = fmaf(crow[e], w[(size_t)e * Ldim + j], acc);
    float q = __fadd_rn(acc, bias[j]);

    const size_t off = (size_t)b * Ldim + j;
    float nrv = nr[off];
    float d   = __fsub_rn(q, nrv);            // q - nr (loss term & ST delta)
    float qst = __fadd_rn(nrv, d);            // straight-through forward value

    quant[off] = __fadd_rn(quant[off], qst);
    cur[off]   = __fsub_rn(cur[off],  qst);

    float s = __fmul_rn(d, d);
    #pragma unroll
    for (int o = 16; o; o >>= 1) s += __shfl_down_sync(0xffffffffu, s, o);
    if ((j & 31) == 0) red[j >> 5] = s;
    __syncthreads();
    if (j == 0) rowloss[b] += red[0] + red[1] + red[2] + red[3];
}

// ---------------------------------------------------------------------------
// Deterministic final loss reduction: loss = 1.25 * sum(rowloss) / (B*L)
// ---------------------------------------------------------------------------
__global__ __launch_bounds__(1024) void loss_finalize_kernel(
    const float* __restrict__ rowloss, float* __restrict__ out)
{
    __shared__ float sm[1024];
    int t = threadIdx.x;
    float s = 0.0f;
    for (int i = t; i < Bsz; i += 1024) s += rowloss[i];
    sm[t] = s;
    __syncthreads();
    for (int o = 512; o; o >>= 1) {
        if (t < o) sm[t] += sm[t + o];
        __syncthreads();
    }
    if (t == 0) out[0] = sm[0] * 1.25f / (float)(Bsz * Ldim);
}

// ---------------------------------------------------------------------------
// Launch
// ---------------------------------------------------------------------------
extern "C" void kernel_launch(void* const* d_in, const int* in_sizes, int n_in,
                              void* d_out, int out_size)
{
    const float* x        = (const float*)d_in[0];
    const float* eps      = (const float*)d_in[1];
    const float* enc_w1   = (const float*)d_in[2];
    const float* enc_b1   = (const float*)d_in[3];
    const float* enc_w2   = (const float*)d_in[4];
    const float* enc_b2   = (const float*)d_in[5];
    const float* enc_w3   = (const float*)d_in[6];
    const float* enc_b3   = (const float*)d_in[7];
    const float* mu_w     = (const float*)d_in[8];
    const float* mu_b     = (const float*)d_in[9];
    const float* var_w    = (const float*)d_in[10];
    const float* var_b    = (const float*)d_in[11];
    const float* dec_w1   = (const float*)d_in[12];
    const float* dec_b1   = (const float*)d_in[13];
    const float* dec_w2   = (const float*)d_in[14];
    const float* dec_b2   = (const float*)d_in[15];
    const float* dec_w3   = (const float*)d_in[16];
    const float* dec_b3   = (const float*)d_in[17];
    const float* ln_g     = (const float*)d_in[18];
    const float* ln_b     = (const float*)d_in[19];
    const float* q_in_w   = (const float*)d_in[20];
    const float* q_in_b   = (const float*)d_in[21];
    const float* codebook = (const float*)d_in[22];
    const float* q_out_w  = (const float*)d_in[23];
    const float* q_out_b  = (const float*)d_in[24];

    float* out   = (float*)d_out;
    float* recon = out;
    float* mu    = out + (size_t)Bsz * DIN;
    float* lv    = mu + (size_t)Bsz * Ldim;
    float* loss  = out + (size_t)Bsz * (DIN + 2 * Ldim);

    float *h1, *h2, *z, *nr, *f, *quant, *rowloss, *cbn;
    int* idx;
    cudaGetSymbolAddress((void**)&h1, g_h1);
    cudaGetSymbolAddress((void**)&h2, g_h2);
    cudaGetSymbolAddress((void**)&z, g_z);
    cudaGetSymbolAddress((void**)&nr, g_nr);
    cudaGetSymbolAddress((void**)&f, g_f);
    cudaGetSymbolAddress((void**)&quant, g_quant);
    cudaGetSymbolAddress((void**)&rowloss, g_rowloss);
    cudaGetSymbolAddress((void**)&cbn, g_cbnorm);
    cudaGetSymbolAddress((void**)&idx, g_idx);

    const int ARGMIN_SMEM = (2 * 128 * 65 + 64) * (int)sizeof(float);
    cudaFuncSetAttribute(argmin_kernel,
                         cudaFuncAttributeMaxDynamicSharedMemorySize,
                         ARGMIN_SMEM);

    // --- encoder ---
    gemm_kernel<true ><<<dim3(Hdim / 64, Bsz / 64), 256>>>(x,  enc_w1, enc_b1, h1, Bsz, Hdim, DIN);
    gemm_kernel<true ><<<dim3(Hdim / 64, Bsz / 64), 256>>>(h1, enc_w2, enc_b2, h2, Bsz, Hdim, Hdim);
    gemm_kernel<false><<<dim3(Hdim / 64, Bsz / 64), 256>>>(h2, enc_w3, enc_b3, h1, Bsz, Hdim, Hdim);
    gemm_kernel<false><<<dim3(Ldim / 64, Bsz / 64), 256>>>(h1, mu_w,  mu_b,  mu, Bsz, Ldim, Hdim);
    gemm_kernel<false><<<dim3(Ldim / 64, Bsz / 64), 256>>>(h1, var_w, var_b, lv, Bsz, Ldim, Hdim);

    // --- codebook norms (all layers) + reparameterize/init ---
    cbnorm_kernel<<<NLq * Kcb, 128>>>(codebook, cbn);
    init_kernel<<<(Bsz * Ldim + 255) / 256, 256>>>(mu, lv, eps, z, quant, rowloss);

    // --- residual quantization layers ---
    for (int i = 0; i < NLq; i++) {
        ln_kernel<<<Bsz, 128>>>(z, ln_g + i * Ldim, ln_b + i * Ldim, nr);
        gemm_kernel<false><<<dim3(Edim / 64, Bsz / 64), 256>>>(
            nr, q_in_w + (size_t)i * Ldim * Edim, q_in_b + i * Edim, f,
            Bsz, Edim, Ldim);
        argmin_kernel<<<Bsz / 64, 256, ARGMIN_SMEM>>>(
            f, codebook + (size_t)i * Kcb * Edim, cbn + i * Kcb, idx);
        gather_update_kernel<<<Bsz, 128>>>(
            idx, codebook + (size_t)i * Kcb * Edim,
            q_out_w + (size_t)i * Edim * Ldim, q_out_b + i * Ldim,
            nr, quant, z, rowloss);
    }

    // --- decoder ---
    gemm_kernel<true ><<<dim3(Hdim / 64, Bsz / 64), 256>>>(quant, dec_w1, dec_b1, h1, Bsz, Hdim, Ldim);
    gemm_kernel<true ><<<dim3(Hdim / 64, Bsz / 64), 256>>>(h1,    dec_w2, dec_b2, h2, Bsz, Hdim, Hdim);
    gemm_kernel<false><<<dim3(DIN  / 64, Bsz / 64), 256>>>(h2,    dec_w3, dec_b3, recon, Bsz, DIN, Hdim);

    // --- loss ---
    loss_finalize_kernel<<<1, 1024>>>(rowloss, loss);
}

// round 8
// speedup vs baseline: 1.8687x; 1.8687x over previous
#include <cuda_runtime.h>
#include <cstdint>
#include <cstddef>

#define Bsz   16384
#define DIN   768
#define Hdim  1024
#define Ldim  128
#define Kcb   8192
#define Edim  128
#define NLq   3

#define PADK  36   // floats per smem row (32 k + pad), 16B-aligned, conflict-free

// ---------------------------------------------------------------------------
// Scratch (device globals; no allocation allowed)
// ---------------------------------------------------------------------------
__device__ float g_h1[Bsz * Hdim];
__device__ float g_h2[Bsz * Hdim];
__device__ float g_z[Bsz * Ldim];       // doubles as "cur"
__device__ float g_nr[Bsz * Ldim];
__device__ float g_f[Bsz * Ldim];
__device__ float g_quant[Bsz * Ldim];
__device__ float g_rowloss[Bsz];
__device__ int   g_idx[Bsz];
__device__ float g_cbnorm[NLq * Kcb];
__device__ float g_wt[5160960];         // all transposed weights [N,K]

#define OFF_E1T 0u
#define OFF_E2T 786432u
#define OFF_E3T 1835008u
#define OFF_MUT 2883584u
#define OFF_VAT 3014656u
#define OFF_D1T 3145728u
#define OFF_D2T 3276800u
#define OFF_D3T 4325376u
#define OFF_QIT 5111808u

// ---------------------------------------------------------------------------
// Helpers
// ---------------------------------------------------------------------------
__device__ __forceinline__ float tf32r(float x) {
    uint32_t u;
    asm("cvt.rna.tf32.f32 %0, %1;" : "=r"(u) : "f"(x));
    return __uint_as_float(u);
}

// split one float4 into tf32 hi/lo and store to padded smem tiles
__device__ __forceinline__ void split2(float* H, float* L, int off, float4 v) {
    float hx = tf32r(v.x), hy = tf32r(v.y), hz = tf32r(v.z), hw = tf32r(v.w);
    *(float4*)(H + off) = make_float4(hx, hy, hz, hw);
    *(float4*)(L + off) = make_float4(
        tf32r(__fsub_rn(v.x, hx)), tf32r(__fsub_rn(v.y, hy)),
        tf32r(__fsub_rn(v.z, hz)), tf32r(__fsub_rn(v.w, hw)));
}

// m16n8k8 tf32 MMA (legacy sm_80+ path; compiles for compute_103)
__device__ __forceinline__ void mma8(float* d, const uint32_t* a, const uint32_t* b) {
    asm volatile(
        "mma.sync.aligned.m16n8k8.row.col.f32.tf32.tf32.f32 "
        "{%0,%1,%2,%3}, {%4,%5,%6,%7}, {%8,%9}, {%0,%1,%2,%3};\n"
        : "+f"(d[0]), "+f"(d[1]), "+f"(d[2]), "+f"(d[3])
        : "r"(a[0]), "r"(a[1]), "r"(a[2]), "r"(a[3]), "r"(b[0]), "r"(b[1]));
}
__device__ __forceinline__ uint32_t fu(float x) { return __float_as_uint(x); }

// ---------------------------------------------------------------------------
// 3xTF32 mma.sync GEMM: C[M,N] = act(A[M,K] @ Bt[N,K]^T + bias[N])
// block 256 (8 warps, 2x4), CTA tile 128x128, warp tile 64x32, k-chunk 32.
// hi/lo split at smem-store; register prefetch of next chunk.
// Dyn smem: 4 * 128*36 floats = 73728 B.
// ---------------------------------------------------------------------------
template <bool RELU>
__global__ __launch_bounds__(256, 1) void gemm_mma(
    const float* __restrict__ A, const float* __restrict__ Bt,
    const float* __restrict__ bias, float* __restrict__ C,
    int M, int N, int K)
{
    extern __shared__ float sm[];
    float* Ah = sm;
    float* Al = sm + 128 * PADK;
    float* Bh = sm + 2 * 128 * PADK;
    float* Bl = sm + 3 * 128 * PADK;
    __shared__ float s_bias[128];

    const int tid = threadIdx.x;
    const int lane = tid & 31;
    const int wid = tid >> 5;
    const int g = lane >> 2, tg = lane & 3;
    const int wm = wid >> 2, wn = wid & 3;
    const int row0 = blockIdx.y * 128, col0 = blockIdx.x * 128;

    if (tid < 128) s_bias[tid] = bias[col0 + tid];

    float acc[4][4][4] = {};

    float4 pa[4], pb[4];
    const int nchunk = K >> 5;
    #pragma unroll
    for (int q = 0; q < 4; q++) {
        int idx = q * 256 + tid, r = idx >> 3, c4 = idx & 7;
        pa[q] = *(const float4*)(A  + (size_t)(row0 + r) * K + c4 * 4);
        pb[q] = *(const float4*)(Bt + (size_t)(col0 + r) * K + c4 * 4);
    }

    for (int c = 0; c < nchunk; c++) {
        #pragma unroll
        for (int q = 0; q < 4; q++) {
            int idx = q * 256 + tid, r = idx >> 3, c4 = idx & 7;
            split2(Ah, Al, r * PADK + c4 * 4, pa[q]);
            split2(Bh, Bl, r * PADK + c4 * 4, pb[q]);
        }
        if (c + 1 < nchunk) {
            #pragma unroll
            for (int q = 0; q < 4; q++) {
                int idx = q * 256 + tid, r = idx >> 3, c4 = idx & 7;
                pa[q] = *(const float4*)(A  + (size_t)(row0 + r) * K + (c + 1) * 32 + c4 * 4);
                pb[q] = *(const float4*)(Bt + (size_t)(col0 + r) * K + (c + 1) * 32 + c4 * 4);
            }
        }
        __syncthreads();

        #pragma unroll
        for (int kb = 0; kb < 4; kb++) {
            uint32_t ah[4][4], al[4][4], bh[4][2], bl[4][2];
            const int kk = kb * 8 + tg;
            #pragma unroll
            for (int mb = 0; mb < 4; mb++) {
                int r = wm * 64 + mb * 16 + g;
                ah[mb][0] = fu(Ah[r * PADK + kk]);
                ah[mb][1] = fu(Ah[(r + 8) * PADK + kk]);
                ah[mb][2] = fu(Ah[r * PADK + kk + 4]);
                ah[mb][3] = fu(Ah[(r + 8) * PADK + kk + 4]);
                al[mb][0] = fu(Al[r * PADK + kk]);
                al[mb][1] = fu(Al[(r + 8) * PADK + kk]);
                al[mb][2] = fu(Al[r * PADK + kk + 4]);
                al[mb][3] = fu(Al[(r + 8) * PADK + kk + 4]);
            }
            #pragma unroll
            for (int nb = 0; nb < 4; nb++) {
                int n = wn * 32 + nb * 8 + g;
                bh[nb][0] = fu(Bh[n * PADK + kk]);
                bh[nb][1] = fu(Bh[n * PADK + kk + 4]);
                bl[nb][0] = fu(Bl[n * PADK + kk]);
                bl[nb][1] = fu(Bl[n * PADK + kk + 4]);
            }
            #pragma unroll
            for (int mb = 0; mb < 4; mb++)
                #pragma unroll
                for (int nb = 0; nb < 4; nb++) {
                    mma8(acc[mb][nb], ah[mb], bh[nb]);
                    mma8(acc[mb][nb], ah[mb], bl[nb]);
                    mma8(acc[mb][nb], al[mb], bh[nb]);
                }
        }
        __syncthreads();
    }

    #pragma unroll
    for (int mb = 0; mb < 4; mb++) {
        int r = row0 + wm * 64 + mb * 16 + g;
        #pragma unroll
        for (int nb = 0; nb < 4; nb++) {
            int ccol = wn * 32 + nb * 8 + 2 * tg;
            float b0 = s_bias[ccol], b1 = s_bias[ccol + 1];
            float v0 = __fadd_rn(acc[mb][nb][0], b0);
            float v1 = __fadd_rn(acc[mb][nb][1], b1);
            float v2 = __fadd_rn(acc[mb][nb][2], b0);
            float v3 = __fadd_rn(acc[mb][nb][3], b1);
            if (RELU) {
                v0 = fmaxf(v0, 0.0f); v1 = fmaxf(v1, 0.0f);
                v2 = fmaxf(v2, 0.0f); v3 = fmaxf(v3, 0.0f);
            }
            *(float2*)&C[(size_t)r * N + col0 + ccol]       = make_float2(v0, v1);
            *(float2*)&C[(size_t)(r + 8) * N + col0 + ccol] = make_float2(v2, v3);
        }
    }
}

// ---------------------------------------------------------------------------
// 3xTF32 mma.sync argmin: 128 rows/CTA over K=8192 codes, 128-code tiles.
// f (hi/lo, 4 k-chunks) resident in smem; codebook chunk streamed + reg-
// prefetched. d = fl(fl(fn+cbn) - fl(2*dot)); first-min tie-break.
// Dyn smem: 10 * 128*36 floats = 184320 B.
// ---------------------------------------------------------------------------
__global__ __launch_bounds__(256, 1) void argmin_mma(
    const float* __restrict__ f, const float* __restrict__ cb,
    const float* __restrict__ cbn, int* __restrict__ idxout)
{
    extern __shared__ float sm[];
    __shared__ float s_fn[128];
    __shared__ float s_cbn[128];
    __shared__ float s_rv[128 * 8];
    __shared__ int   s_ri[128 * 8];

    float* Bh = sm + 8 * 128 * PADK;
    float* Bl = sm + 9 * 128 * PADK;

    const int tid = threadIdx.x;
    const int lane = tid & 31;
    const int wid = tid >> 5;
    const int g = lane >> 2, tg = lane & 3;
    const int wm = wid >> 1, wn = wid & 1;
    const int row0 = blockIdx.x * 128;

    // init: 128 threads each own one row — fn (reference order) + hi/lo split
    if (tid < 128) {
        const float4* fr = (const float4*)(f + (size_t)(row0 + tid) * Edim);
        float s = 0.0f;
        #pragma unroll
        for (int q = 0; q < 32; q++) {
            float4 v = fr[q];
            s = __fadd_rn(s, __fmul_rn(v.x, v.x));
            s = __fadd_rn(s, __fmul_rn(v.y, v.y));
            s = __fadd_rn(s, __fmul_rn(v.z, v.z));
            s = __fadd_rn(s, __fmul_rn(v.w, v.w));
            int ch = q >> 3;
            split2(sm + ch * 128 * PADK, sm + (4 + ch) * 128 * PADK,
                   tid * PADK + (q & 7) * 4, v);
        }
        s_fn[tid] = s;
    }
    __syncthreads();

    float fnr[2][2];
    #pragma unroll
    for (int mb = 0; mb < 2; mb++)
        #pragma unroll
        for (int h = 0; h < 2; h++)
            fnr[mb][h] = s_fn[wm * 32 + mb * 16 + h * 8 + g];

    float bv[2][2] = {{3.4e38f, 3.4e38f}, {3.4e38f, 3.4e38f}};
    int   bi[2][2] = {{0, 0}, {0, 0}};
    float acc[2][8][4] = {};

    float4 pb[4];
    #pragma unroll
    for (int q = 0; q < 4; q++) {
        int idx = q * 256 + tid, r = idx >> 3, c4 = idx & 7;
        pb[q] = *(const float4*)(cb + (size_t)r * Edim + c4 * 4);
    }

    for (int gc = 0; gc < (Kcb / 128) * 4; gc++) {
        const int tile = gc >> 2, ch = gc & 3;
        #pragma unroll
        for (int q = 0; q < 4; q++) {
            int idx = q * 256 + tid, r = idx >> 3, c4 = idx & 7;
            split2(Bh, Bl, r * PADK + c4 * 4, pb[q]);
        }
        if (ch == 0 && tid < 128) s_cbn[tid] = cbn[tile * 128 + tid];
        if (gc + 1 < (Kcb / 128) * 4) {
            int nt = (gc + 1) >> 2, nc = (gc + 1) & 3;
            #pragma unroll
            for (int q = 0; q < 4; q++) {
                int idx = q * 256 + tid, r = idx >> 3, c4 = idx & 7;
                pb[q] = *(const float4*)(cb + (size_t)(nt * 128 + r) * Edim + nc * 32 + c4 * 4);
            }
        }
        __syncthreads();

        float* Ah = sm + ch * 128 * PADK;
        float* Al = sm + (4 + ch) * 128 * PADK;
        #pragma unroll
        for (int kb = 0; kb < 4; kb++) {
            uint32_t ah[2][4], al[2][4], bh[8][2], bl[8][2];
            const int kk = kb * 8 + tg;
            #pragma unroll
            for (int mb = 0; mb < 2; mb++) {
                int r = wm * 32 + mb * 16 + g;
                ah[mb][0] = fu(Ah[r * PADK + kk]);
                ah[mb][1] = fu(Ah[(r + 8) * PADK + kk]);
                ah[mb][2] = fu(Ah[r * PADK + kk + 4]);
                ah[mb][3] = fu(Ah[(r + 8) * PADK + kk + 4]);
                al[mb][0] = fu(Al[r * PADK + kk]);
                al[mb][1] = fu(Al[(r + 8) * PADK + kk]);
                al[mb][2] = fu(Al[r * PADK + kk + 4]);
                al[mb][3] = fu(Al[(r + 8) * PADK + kk + 4]);
            }
            #pragma unroll
            for (int nb = 0; nb < 8; nb++) {
                int n = wn * 64 + nb * 8 + g;
                bh[nb][0] = fu(Bh[n * PADK + kk]);
                bh[nb][1] = fu(Bh[n * PADK + kk + 4]);
                bl[nb][0] = fu(Bl[n * PADK + kk]);
                bl[nb][1] = fu(Bl[n * PADK + kk + 4]);
            }
            #pragma unroll
            for (int mb = 0; mb < 2; mb++)
                #pragma unroll
                for (int nb = 0; nb < 8; nb++) {
                    mma8(acc[mb][nb], ah[mb], bh[nb]);
                    mma8(acc[mb][nb], ah[mb], bl[nb]);
                    mma8(acc[mb][nb], al[mb], bh[nb]);
                }
        }

        if (ch == 3) {
            #pragma unroll
            for (int mb = 0; mb < 2; mb++)
                #pragma unroll
                for (int nb = 0; nb < 8; nb++) {
                    int loc = wn * 64 + nb * 8 + 2 * tg;
                    int base = tile * 128 + loc;
                    float c0 = s_cbn[loc], c1 = s_cbn[loc + 1];
                    float d00 = __fsub_rn(__fadd_rn(fnr[mb][0], c0),
                                          __fmul_rn(2.0f, acc[mb][nb][0]));
                    float d01 = __fsub_rn(__fadd_rn(fnr[mb][0], c1),
                                          __fmul_rn(2.0f, acc[mb][nb][1]));
                    float d10 = __fsub_rn(__fadd_rn(fnr[mb][1], c0),
                                          __fmul_rn(2.0f, acc[mb][nb][2]));
                    float d11 = __fsub_rn(__fadd_rn(fnr[mb][1], c1),
                                          __fmul_rn(2.0f, acc[mb][nb][3]));
                    if (d00 < bv[mb][0]) { bv[mb][0] = d00; bi[mb][0] = base; }
                    if (d01 < bv[mb][0]) { bv[mb][0] = d01; bi[mb][0] = base + 1; }
                    if (d10 < bv[mb][1]) { bv[mb][1] = d10; bi[mb][1] = base; }
                    if (d11 < bv[mb][1]) { bv[mb][1] = d11; bi[mb][1] = base + 1; }
                    acc[mb][nb][0] = 0.0f; acc[mb][nb][1] = 0.0f;
                    acc[mb][nb][2] = 0.0f; acc[mb][nb][3] = 0.0f;
                }
        }
        __syncthreads();
    }

    const int slot = wn * 4 + tg;
    #pragma unroll
    for (int mb = 0; mb < 2; mb++)
        #pragma unroll
        for (int h = 0; h < 2; h++) {
            int r = wm * 32 + mb * 16 + h * 8 + g;
            s_rv[r * 8 + slot] = bv[mb][h];
            s_ri[r * 8 + slot] = bi[mb][h];
        }
    __syncthreads();
    if (tid < 128) {
        float v = s_rv[tid * 8];
        int   ii = s_ri[tid * 8];
        #pragma unroll
        for (int s = 1; s < 8; s++) {
            float w = s_rv[tid * 8 + s];
            int   jj = s_ri[tid * 8 + s];
            if (w < v || (w == v && jj < ii)) { v = w; ii = jj; }
        }
        idxout[row0 + tid] = ii;
    }
}

// ---------------------------------------------------------------------------
// Tiled transpose: dst[Ccol,R] = src[R,Ccol]^T
// ---------------------------------------------------------------------------
__global__ __launch_bounds__(256) void transpose_kernel(
    const float* __restrict__ src, float* __restrict__ dst, int R, int Ccol)
{
    __shared__ float t[32][33];
    int bx = blockIdx.x * 32, by = blockIdx.y * 32;
    #pragma unroll
    for (int j = 0; j < 32; j += 8)
        t[threadIdx.y + j][threadIdx.x] =
            src[(size_t)(by + threadIdx.y + j) * Ccol + bx + threadIdx.x];
    __syncthreads();
    #pragma unroll
    for (int j = 0; j < 32; j += 8)
        dst[(size_t)(bx + threadIdx.y + j) * R + by + threadIdx.x] =
            t[threadIdx.x][threadIdx.y + j];
}

// ---------------------------------------------------------------------------
// LayerNorm (rows of 128, eps=1e-5, biased var), IEEE sqrt+div
// ---------------------------------------------------------------------------
__global__ __launch_bounds__(128) void ln_kernel(
    const float* __restrict__ x, const float* __restrict__ g,
    const float* __restrict__ b, float* __restrict__ out)
{
    const int row = blockIdx.x;
    const int j = threadIdx.x;
    __shared__ float sm[4];

    float v = x[(size_t)row * Ldim + j];

    float s = v;
    #pragma unroll
    for (int o = 16; o; o >>= 1) s += __shfl_down_sync(0xffffffffu, s, o);
    if ((j & 31) == 0) sm[j >> 5] = s;
    __syncthreads();
    float mean = (sm[0] + sm[1] + sm[2] + sm[3]) * (1.0f / 128.0f);
    __syncthreads();

    float t = __fsub_rn(v, mean);
    s = __fmul_rn(t, t);
    #pragma unroll
    for (int o = 16; o; o >>= 1) s += __shfl_down_sync(0xffffffffu, s, o);
    if ((j & 31) == 0) sm[j >> 5] = s;
    __syncthreads();
    float var = (sm[0] + sm[1] + sm[2] + sm[3]) * (1.0f / 128.0f);

    float denom = sqrtf(__fadd_rn(var, 1e-5f));
    float r = __fdiv_rn(t, denom);
    out[(size_t)row * Ldim + j] = __fadd_rn(__fmul_rn(r, g[j]), b[j]);
}

// ---------------------------------------------------------------------------
// Codebook row squared norms
// ---------------------------------------------------------------------------
__global__ __launch_bounds__(128) void cbnorm_kernel(
    const float* __restrict__ cb, float* __restrict__ out)
{
    const int r = blockIdx.x;
    const int j = threadIdx.x;
    __shared__ float sm[4];
    float v = cb[(size_t)r * Edim + j];
    float s = __fmul_rn(v, v);
    #pragma unroll
    for (int o = 16; o; o >>= 1) s += __shfl_down_sync(0xffffffffu, s, o);
    if ((j & 31) == 0) sm[j >> 5] = s;
    __syncthreads();
    if (j == 0) out[r] = sm[0] + sm[1] + sm[2] + sm[3];
}

// ---------------------------------------------------------------------------
// Reparameterize + init
// ---------------------------------------------------------------------------
__global__ __launch_bounds__(256) void init_kernel(
    const float* __restrict__ mu, const float* __restrict__ lv,
    const float* __restrict__ eps, float* __restrict__ z,
    float* __restrict__ quant, float* __restrict__ rowloss)
{
    int i = blockIdx.x * blockDim.x + threadIdx.x;
    if (i < Bsz * Ldim) {
        float e = expf(__fmul_rn(0.5f, lv[i]));
        float zz = __fadd_rn(mu[i], __fmul_rn(eps[i], e));
        z[i] = zz;
        quant[i] = 0.0f;
    }
    if (i < Bsz) rowloss[i] = 0.0f;
}

// ---------------------------------------------------------------------------
// Gather + q_out projection + straight-through update + rowloss
// ---------------------------------------------------------------------------
__global__ __launch_bounds__(128) void gather_update_kernel(
    const int* __restrict__ idx, const float* __restrict__ cb,
    const float* __restrict__ w, const float* __restrict__ bias,
    const float* __restrict__ nr, float* __restrict__ quant,
    float* __restrict__ cur, float* __restrict__ rowloss)
{
    const int b = blockIdx.x;
    const int j = threadIdx.x;
    __shared__ float crow[128];
    __shared__ float red[4];

    const int k = idx[b];
    crow[j] = cb[(size_t)k * Edim + j];
    __syncthreads();

    float acc = 0.0f;
    #pragma unroll 8
    for (int e = 0; e < 128; e++)
        acc = fmaf(crow[e], w[(size_t)e * Ldim + j], acc);
    float q = __fadd_rn(acc, bias[j]);

    const size_t off = (size_t)b * Ldim + j;
    float nrv = nr[off];
    float d   = __fsub_rn(q, nrv);
    float qst = __fadd_rn(nrv, d);

    quant[off] = __fadd_rn(quant[off], qst);
    cur[off]   = __fsub_rn(cur[off],  qst);

    float s = __fmul_rn(d, d);
    #pragma unroll
    for (int o = 16; o; o >>= 1) s += __shfl_down_sync(0xffffffffu, s, o);
    if ((j & 31) == 0) red[j >> 5] = s;
    __syncthreads();
    if (j == 0) rowloss[b] += red[0] + red[1] + red[2] + red[3];
}

// ---------------------------------------------------------------------------
// Final loss
// ---------------------------------------------------------------------------
__global__ __launch_bounds__(1024) void loss_finalize_kernel(
    const float* __restrict__ rowloss, float* __restrict__ out)
{
    __shared__ float sm[1024];
    int t = threadIdx.x;
    float s = 0.0f;
    for (int i = t; i < Bsz; i += 1024) s += rowloss[i];
    sm[t] = s;
    __syncthreads();
    for (int o = 512; o; o >>= 1) {
        if (t < o) sm[t] += sm[t + o];
        __syncthreads();
    }
    if (t == 0) out[0] = sm[0] * 1.25f / (float)(Bsz * Ldim);
}

// ---------------------------------------------------------------------------
// Launch
// ---------------------------------------------------------------------------
extern "C" void kernel_launch(void* const* d_in, const int* in_sizes, int n_in,
                              void* d_out, int out_size)
{
    const float* x        = (const float*)d_in[0];
    const float* eps      = (const float*)d_in[1];
    const float* enc_w1   = (const float*)d_in[2];
    const float* enc_b1   = (const float*)d_in[3];
    const float* enc_w2   = (const float*)d_in[4];
    const float* enc_b2   = (const float*)d_in[5];
    const float* enc_w3   = (const float*)d_in[6];
    const float* enc_b3   = (const float*)d_in[7];
    const float* mu_w     = (const float*)d_in[8];
    const float* mu_b     = (const float*)d_in[9];
    const float* var_w    = (const float*)d_in[10];
    const float* var_b    = (const float*)d_in[11];
    const float* dec_w1   = (const float*)d_in[12];
    const float* dec_b1   = (const float*)d_in[13];
    const float* dec_w2   = (const float*)d_in[14];
    const float* dec_b2   = (const float*)d_in[15];
    const float* dec_w3   = (const float*)d_in[16];
    const float* dec_b3   = (const float*)d_in[17];
    const float* ln_g     = (const float*)d_in[18];
    const float* ln_b     = (const float*)d_in[19];
    const float* q_in_w   = (const float*)d_in[20];
    const float* q_in_b   = (const float*)d_in[21];
    const float* codebook = (const float*)d_in[22];
    const float* q_out_w  = (const float*)d_in[23];
    const float* q_out_b  = (const float*)d_in[24];

    float* out   = (float*)d_out;
    float* recon = out;
    float* mu    = out + (size_t)Bsz * DIN;
    float* lv    = mu + (size_t)Bsz * Ldim;
    float* loss  = out + (size_t)Bsz * (DIN + 2 * Ldim);

    float *h1, *h2, *z, *nr, *f, *quant, *rowloss, *cbn, *wt;
    int* idx;
    cudaGetSymbolAddress((void**)&h1, g_h1);
    cudaGetSymbolAddress((void**)&h2, g_h2);
    cudaGetSymbolAddress((void**)&z, g_z);
    cudaGetSymbolAddress((void**)&nr, g_nr);
    cudaGetSymbolAddress((void**)&f, g_f);
    cudaGetSymbolAddress((void**)&quant, g_quant);
    cudaGetSymbolAddress((void**)&rowloss, g_rowloss);
    cudaGetSymbolAddress((void**)&cbn, g_cbnorm);
    cudaGetSymbolAddress((void**)&idx, g_idx);
    cudaGetSymbolAddress((void**)&wt, g_wt);

    const int GEMM_SMEM   = 4  * 128 * PADK * (int)sizeof(float);   // 73728
    const int ARGMIN_SMEM = 10 * 128 * PADK * (int)sizeof(float);   // 184320
    cudaFuncSetAttribute(gemm_mma<true>,  cudaFuncAttributeMaxDynamicSharedMemorySize, GEMM_SMEM);
    cudaFuncSetAttribute(gemm_mma<false>, cudaFuncAttributeMaxDynamicSharedMemorySize, GEMM_SMEM);
    cudaFuncSetAttribute(argmin_mma,      cudaFuncAttributeMaxDynamicSharedMemorySize, ARGMIN_SMEM);

    dim3 tb(32, 8);

    // --- weight transposes: W[K,N] -> Wt[N,K] ---
    transpose_kernel<<<dim3(Hdim/32, DIN/32),  tb>>>(enc_w1, wt + OFF_E1T, DIN,  Hdim);
    transpose_kernel<<<dim3(Hdim/32, Hdim/32), tb>>>(enc_w2, wt + OFF_E2T, Hdim, Hdim);
    transpose_kernel<<<dim3(Hdim/32, Hdim/32), tb>>>(enc_w3, wt + OFF_E3T, Hdim, Hdim);
    transpose_kernel<<<dim3(Ldim/32, Hdim/32), tb>>>(mu_w,   wt + OFF_MUT, Hdim, Ldim);
    transpose_kernel<<<dim3(Ldim/32, Hdim/32), tb>>>(var_w,  wt + OFF_VAT, Hdim, Ldim);
    transpose_kernel<<<dim3(Hdim/32, Ldim/32), tb>>>(dec_w1, wt + OFF_D1T, Ldim, Hdim);
    transpose_kernel<<<dim3(Hdim/32, Hdim/32), tb>>>(dec_w2, wt + OFF_D2T, Hdim, Hdim);
    transpose_kernel<<<dim3(DIN/32,  Hdim/32), tb>>>(dec_w3, wt + OFF_D3T, Hdim, DIN);
    for (int i = 0; i < NLq; i++)
        transpose_kernel<<<dim3(Edim/32, Ldim/32), tb>>>(
            q_in_w + (size_t)i * Ldim * Edim, wt + OFF_QIT + (size_t)i * Edim * Ldim,
            Ldim, Edim);

    // --- encoder ---
    gemm_mma<true ><<<dim3(Hdim/128, Bsz/128), 256, GEMM_SMEM>>>(x,  wt + OFF_E1T, enc_b1, h1, Bsz, Hdim, DIN);
    gemm_mma<true ><<<dim3(Hdim/128, Bsz/128), 256, GEMM_SMEM>>>(h1, wt + OFF_E2T, enc_b2, h2, Bsz, Hdim, Hdim);
    gemm_mma<false><<<dim3(Hdim/128, Bsz/128), 256, GEMM_SMEM>>>(h2, wt + OFF_E3T, enc_b3, h1, Bsz, Hdim, Hdim);
    gemm_mma<false><<<dim3(Ldim/128, Bsz/128), 256, GEMM_SMEM>>>(h1, wt + OFF_MUT, mu_b,  mu, Bsz, Ldim, Hdim);
    gemm_mma<false><<<dim3(Ldim/128, Bsz/128), 256, GEMM_SMEM>>>(h1, wt + OFF_VAT, var_b, lv, Bsz, Ldim, Hdim);

    // --- codebook norms + reparameterize/init ---
    cbnorm_kernel<<<NLq * Kcb, 128>>>(codebook, cbn);
    init_kernel<<<(Bsz * Ldim + 255) / 256, 256>>>(mu, lv, eps, z, quant, rowloss);

    // --- residual quantization ---
    for (int i = 0; i < NLq; i++) {
        ln_kernel<<<Bsz, 128>>>(z, ln_g + i * Ldim, ln_b + i * Ldim, nr);
        gemm_mma<false><<<dim3(Edim/128, Bsz/128), 256, GEMM_SMEM>>>(
            nr, wt + OFF_QIT + (size_t)i * Edim * Ldim, q_in_b + i * Edim, f,
            Bsz, Edim, Ldim);
        argmin_mma<<<Bsz / 128, 256, ARGMIN_SMEM>>>(
            f, codebook + (size_t)i * Kcb * Edim, cbn + i * Kcb, idx);
        gather_update_kernel<<<Bsz, 128>>>(
            idx, codebook + (size_t)i * Kcb * Edim,
            q_out_w + (size_t)i * Edim * Ldim, q_out_b + i * Ldim,
            nr, quant, z, rowloss);
    }

    // --- decoder ---
    gemm_mma<true ><<<dim3(Hdim/128, Bsz/128), 256, GEMM_SMEM>>>(quant, wt + OFF_D1T, dec_b1, h1, Bsz, Hdim, Ldim);
    gemm_mma<true ><<<dim3(Hdim/128, Bsz/128), 256, GEMM_SMEM>>>(h1,    wt + OFF_D2T, dec_b2, h2, Bsz, Hdim, Hdim);
    gemm_mma<false><<<dim3(DIN/128,  Bsz/128), 256, GEMM_SMEM>>>(h2,    wt + OFF_D3T, dec_b3, recon, Bsz, DIN, Hdim);

    // --- loss ---
    loss_finalize_kernel<<<1, 1024>>>(rowloss, loss);
}